// round 1
// baseline (speedup 1.0000x reference)
#include <cuda_runtime.h>
#include <cstdint>

// Problem constants
#define BATCH   8
#define CIN     32
#define COUT    64
#define HW      (512 * 512)          // 262144, divisible by TILE
#define NPIX    (BATCH * HW)         // 2,097,152 pixels
#define TILE    256                  // pixels per block
#define NTHREADS 256

// Shared layout (dynamic):
//   xs  : float  [CIN][TILE]      = 8192 floats (32 KB)
//   ws2 : float2 [CIN][COUT]      = 4096 ull... (2048 float2 = 16 KB), weights pre-packed (w,w)
//   bs  : float  [COUT]           = 64 floats
#define SMEM_FLOATS (CIN * TILE + CIN * COUT * 2 + COUT)

__device__ __forceinline__ void fma2(unsigned long long& d,
                                     unsigned long long a,
                                     unsigned long long b) {
    // packed dual fp32 FMA: d = a * b + d   (two independent fp32 lanes)
    asm("fma.rn.f32x2 %0, %1, %2, %0;" : "+l"(d) : "l"(a), "l"(b));
}

__global__ void __launch_bounds__(NTHREADS, 1)
spconv_pw_kernel(const float* __restrict__ x,
                 const float* __restrict__ Wg,
                 const float* __restrict__ bias,
                 float* __restrict__ out) {
    extern __shared__ float sm[];
    float*  xs  = sm;                                   // [CIN][TILE]
    float2* ws2 = (float2*)(sm + CIN * TILE);           // [CIN][COUT]
    float*  bs  = (float*)(sm + CIN * TILE + CIN * COUT * 2);

    const int tid = threadIdx.x;

    // tile -> (batch, hw offset). HW % TILE == 0, so a tile never crosses batches.
    const long long p0  = (long long)blockIdx.x * TILE;
    const int       b   = (int)(p0 / HW);
    const int       hw0 = (int)(p0 % HW);

    // ---- stage weights (packed (w,w)) and bias ----
    for (int i = tid; i < CIN * COUT; i += NTHREADS) {
        float w = Wg[i];
        ws2[i] = make_float2(w, w);
    }
    if (tid < COUT) bs[tid] = bias[tid];

    // ---- stage x tile: 32 channels x 256 pixels, float4 global loads ----
    const float* xb = x + (long long)b * CIN * HW + hw0;
    #pragma unroll
    for (int i = tid; i < CIN * (TILE / 4); i += NTHREADS) {
        int c = i >> 6;      // i / (TILE/4)
        int q = i & 63;      // i % (TILE/4)
        float4 v = *(const float4*)(xb + (long long)c * HW + q * 4);
        *(float4*)(&xs[c * TILE + q * 4]) = v;
    }
    __syncthreads();

    // thread mapping: og = output group of 16, pg = pixel group of 4
    const int og = tid >> 6;   // 0..3
    const int pg = tid & 63;   // 0..63

    // accumulators: 16 outputs x 2 pixel-pairs, as packed f32x2
    unsigned long long acc[32];
    #pragma unroll
    for (int i = 0; i < 32; ++i) acc[i] = 0ULL;   // (0.0f, 0.0f)

    // activity masks: OR of |x| bit patterns per pixel (handles -0.0 as zero)
    unsigned long long m01 = 0ULL, m23 = 0ULL;
    const unsigned long long ABSM = 0x7FFFFFFF7FFFFFFFULL;

    const float*  xsp = xs + pg * 4;
    const float2* wsp = ws2 + og * 16;

    #pragma unroll 8
    for (int c = 0; c < CIN; ++c) {
        // x pixels p0..p3 as two packed f32x2 (LDS.128)
        ulonglong2 xq = *(const ulonglong2*)(xsp + c * TILE);
        m01 |= (xq.x & ABSM);
        m23 |= (xq.y & ABSM);

        // 16 packed weights for this channel (8 x LDS.128, warp-broadcast)
        const ulonglong2* wrow = (const ulonglong2*)(wsp + c * COUT);
        #pragma unroll
        for (int j = 0; j < 8; ++j) {
            ulonglong2 wv = wrow[j];
            // outputs o = og*16 + 2j and 2j+1, pixel pairs (p0,p1) and (p2,p3)
            fma2(acc[4 * j + 0], xq.x, wv.x);
            fma2(acc[4 * j + 1], xq.y, wv.x);
            fma2(acc[4 * j + 2], xq.x, wv.y);
            fma2(acc[4 * j + 3], xq.y, wv.y);
        }
    }

    // per-pixel active flags
    const bool a0 = (unsigned)(m01)        != 0u;
    const bool a1 = (unsigned)(m01 >> 32)  != 0u;
    const bool a2 = (unsigned)(m23)        != 0u;
    const bool a3 = (unsigned)(m23 >> 32)  != 0u;

    // ---- epilogue: add bias where active, zero elsewhere; STG.128 per output ----
    float* ob = out + ((long long)b * COUT) * HW + hw0 + pg * 4;
    #pragma unroll
    for (int j = 0; j < 8; ++j) {
        int o0 = og * 16 + 2 * j;
        float b0 = bs[o0];
        float b1 = bs[o0 + 1];

        float2 v01 = *(float2*)&acc[4 * j + 0];   // out o0, pixels 0,1
        float2 v23 = *(float2*)&acc[4 * j + 1];   // out o0, pixels 2,3
        float2 u01 = *(float2*)&acc[4 * j + 2];   // out o0+1, pixels 0,1
        float2 u23 = *(float2*)&acc[4 * j + 3];   // out o0+1, pixels 2,3

        float4 r0;
        r0.x = a0 ? (v01.x + b0) : 0.0f;
        r0.y = a1 ? (v01.y + b0) : 0.0f;
        r0.z = a2 ? (v23.x + b0) : 0.0f;
        r0.w = a3 ? (v23.y + b0) : 0.0f;
        *(float4*)(ob + (long long)o0 * HW) = r0;

        float4 r1;
        r1.x = a0 ? (u01.x + b1) : 0.0f;
        r1.y = a1 ? (u01.y + b1) : 0.0f;
        r1.z = a2 ? (u23.x + b1) : 0.0f;
        r1.w = a3 ? (u23.y + b1) : 0.0f;
        *(float4*)(ob + (long long)(o0 + 1) * HW) = r1;
    }
}

extern "C" void kernel_launch(void* const* d_in, const int* in_sizes, int n_in,
                              void* d_out, int out_size) {
    const float* x  = (const float*)d_in[0];
    const float* Wg = (const float*)d_in[1];
    const float* bi = (const float*)d_in[2];
    float* out = (float*)d_out;

    const int smem_bytes = SMEM_FLOATS * (int)sizeof(float);  // 49408 > 48KB static limit
    cudaFuncSetAttribute(spconv_pw_kernel,
                         cudaFuncAttributeMaxDynamicSharedMemorySize, smem_bytes);

    const int grid = NPIX / TILE;   // 8192
    spconv_pw_kernel<<<grid, NTHREADS, smem_bytes>>>(x, Wg, bi, out);
}

// round 2
// speedup vs baseline: 1.4645x; 1.4645x over previous
#include <cuda_runtime.h>
#include <cstdint>

// Problem constants
#define BATCH   8
#define CIN     32
#define COUT    64
#define HW      (512 * 512)          // 262144, divisible by TILE
#define NPIX    (BATCH * HW)         // 2,097,152 pixels
#define TILE    128                  // pixels per block
#define NTHREADS 256

// Shared layout (dynamic):
//   xs  : float  [CIN][TILE]      = 4096 floats (16 KB)
//   ws2 : float2 [CIN][COUT]      = 2048 float2 (16 KB), weights pre-packed (w,w)
//   bs  : float  [COUT]
#define SMEM_FLOATS (CIN * TILE + CIN * COUT * 2 + COUT)

__device__ __forceinline__ void fma2(unsigned long long& d,
                                     unsigned long long a,
                                     unsigned long long b) {
    // packed dual fp32 FMA: d = a * b + d   (two independent fp32 lanes)
    asm("fma.rn.f32x2 %0, %1, %2, %0;" : "+l"(d) : "l"(a), "l"(b));
}

__global__ void __launch_bounds__(NTHREADS, 3)
spconv_pw_kernel(const float* __restrict__ x,
                 const float* __restrict__ Wg,
                 const float* __restrict__ bias,
                 float* __restrict__ out) {
    extern __shared__ float sm[];
    float*  xs  = sm;                                   // [CIN][TILE]
    float2* ws2 = (float2*)(sm + CIN * TILE);           // [CIN][COUT]
    float*  bs  = (float*)(sm + CIN * TILE + CIN * COUT * 2);

    const int tid = threadIdx.x;

    // tile -> (batch, hw offset). HW % TILE == 0, so a tile never crosses batches.
    const long long p0  = (long long)blockIdx.x * TILE;
    const int       b   = (int)(p0 / HW);
    const int       hw0 = (int)(p0 % HW);

    // ---- stage weights (packed (w,w)) and bias ----
    #pragma unroll
    for (int i = tid; i < CIN * COUT; i += NTHREADS) {
        float w = Wg[i];
        ws2[i] = make_float2(w, w);
    }
    if (tid < COUT) bs[tid] = bias[tid];

    // ---- stage x tile: 32 channels x 128 pixels, float4 global loads ----
    const float* xb = x + (long long)b * CIN * HW + hw0;
    #pragma unroll
    for (int i = tid; i < CIN * (TILE / 4); i += NTHREADS) {
        int c = i >> 5;      // i / (TILE/4)
        int q = i & 31;      // i % (TILE/4)
        float4 v = *(const float4*)(xb + (long long)c * HW + q * 4);
        *(float4*)(&xs[c * TILE + q * 4]) = v;
    }
    __syncthreads();

    // thread mapping: og = output group of 8, pg = pixel group of 4
    const int og = tid >> 5;   // 0..7
    const int pg = tid & 31;   // 0..31  (lanes of a warp -> consecutive pixel groups)

    // accumulators: 8 outputs x 2 pixel-pairs, as packed f32x2
    unsigned long long acc[16];
    #pragma unroll
    for (int i = 0; i < 16; ++i) acc[i] = 0ULL;   // (0.0f, 0.0f)

    // activity masks: OR of |x| bit patterns per pixel (handles -0.0 as zero)
    unsigned long long m01 = 0ULL, m23 = 0ULL;
    const unsigned long long ABSM = 0x7FFFFFFF7FFFFFFFULL;

    const float*  xsp = xs + pg * 4;
    const float2* wsp = ws2 + og * 8;

    #pragma unroll
    for (int c = 0; c < CIN; ++c) {
        // x pixels p0..p3 as two packed f32x2 (one LDS.128, coalesced across warp)
        ulonglong2 xq = *(const ulonglong2*)(xsp + c * TILE);
        m01 |= (xq.x & ABSM);
        m23 |= (xq.y & ABSM);

        // 8 packed weights for this channel (4 x LDS.128, warp-broadcast)
        const ulonglong2* wrow = (const ulonglong2*)(wsp + c * COUT);
        #pragma unroll
        for (int j = 0; j < 4; ++j) {
            ulonglong2 wv = wrow[j];
            // outputs o = og*8 + 2j and 2j+1, pixel pairs (p0,p1) and (p2,p3)
            fma2(acc[4 * j + 0], xq.x, wv.x);
            fma2(acc[4 * j + 1], xq.y, wv.x);
            fma2(acc[4 * j + 2], xq.x, wv.y);
            fma2(acc[4 * j + 3], xq.y, wv.y);
        }
    }

    // per-pixel active flags
    const bool a0 = (unsigned)(m01)        != 0u;
    const bool a1 = (unsigned)(m01 >> 32)  != 0u;
    const bool a2 = (unsigned)(m23)        != 0u;
    const bool a3 = (unsigned)(m23 >> 32)  != 0u;

    // ---- epilogue: add bias where active, zero elsewhere; STG.128 per output ----
    float* ob = out + ((long long)b * COUT) * HW + hw0 + pg * 4;
    #pragma unroll
    for (int j = 0; j < 4; ++j) {
        int o0 = og * 8 + 2 * j;
        float b0 = bs[o0];
        float b1 = bs[o0 + 1];

        float2 v01 = *(float2*)&acc[4 * j + 0];   // out o0,   pixels 0,1
        float2 v23 = *(float2*)&acc[4 * j + 1];   // out o0,   pixels 2,3
        float2 u01 = *(float2*)&acc[4 * j + 2];   // out o0+1, pixels 0,1
        float2 u23 = *(float2*)&acc[4 * j + 3];   // out o0+1, pixels 2,3

        float4 r0;
        r0.x = a0 ? (v01.x + b0) : 0.0f;
        r0.y = a1 ? (v01.y + b0) : 0.0f;
        r0.z = a2 ? (v23.x + b0) : 0.0f;
        r0.w = a3 ? (v23.y + b0) : 0.0f;
        *(float4*)(ob + (long long)o0 * HW) = r0;

        float4 r1;
        r1.x = a0 ? (u01.x + b1) : 0.0f;
        r1.y = a1 ? (u01.y + b1) : 0.0f;
        r1.z = a2 ? (u23.x + b1) : 0.0f;
        r1.w = a3 ? (u23.y + b1) : 0.0f;
        *(float4*)(ob + (long long)(o0 + 1) * HW) = r1;
    }
}

extern "C" void kernel_launch(void* const* d_in, const int* in_sizes, int n_in,
                              void* d_out, int out_size) {
    const float* x  = (const float*)d_in[0];
    const float* Wg = (const float*)d_in[1];
    const float* bi = (const float*)d_in[2];
    float* out = (float*)d_out;

    const int smem_bytes = SMEM_FLOATS * (int)sizeof(float);  // ~33 KB
    cudaFuncSetAttribute(spconv_pw_kernel,
                         cudaFuncAttributeMaxDynamicSharedMemorySize, smem_bytes);

    const int grid = NPIX / TILE;   // 16384
    spconv_pw_kernel<<<grid, NTHREADS, smem_bytes>>>(x, Wg, bi, out);
}

// round 3
// speedup vs baseline: 1.6960x; 1.1581x over previous
#include <cuda_runtime.h>
#include <cstdint>

// Problem constants
#define BATCH   8
#define CIN     32
#define COUT    64
#define HW      (512 * 512)          // 262144, divisible by TILE
#define NPIX    (BATCH * HW)         // 2,097,152 pixels
#define TILE    128                  // pixels per block
#define NTHREADS 256

// Shared layout (dynamic):
//   xs : float [CIN][TILE]  = 4096 floats (16 KB)
//   wn : float [CIN][COUT]  = 2048 floats (8 KB)  -- natural order, no duplication
//   bs : float [COUT]
#define SMEM_FLOATS (CIN * TILE + CIN * COUT + COUT)

__device__ __forceinline__ void fma2(unsigned long long& d,
                                     unsigned long long a,
                                     unsigned long long b) {
    // packed dual fp32 FMA: d = a * b + d
    asm("fma.rn.f32x2 %0, %1, %2, %0;" : "+l"(d) : "l"(a), "l"(b));
}

__device__ __forceinline__ unsigned long long dup2(float v) {
    // build (v, v) as a packed f32x2
    unsigned long long r;
    asm("mov.b64 %0, {%1, %1};" : "=l"(r) : "f"(v));
    return r;
}

__device__ __forceinline__ unsigned long long add2(unsigned long long a,
                                                   unsigned long long b) {
    unsigned long long r;
    asm("add.rn.f32x2 %0, %1, %2;" : "=l"(r) : "l"(a), "l"(b));
    return r;
}

__global__ void __launch_bounds__(NTHREADS, 3)
spconv_pw_kernel(const float* __restrict__ x,
                 const float* __restrict__ Wg,
                 const float* __restrict__ bias,
                 float* __restrict__ out) {
    extern __shared__ float sm[];
    float* xs = sm;                          // [CIN][TILE]
    float* wn = sm + CIN * TILE;             // [CIN][COUT] natural
    float* bs = wn + CIN * COUT;             // [COUT]

    const int tid = threadIdx.x;

    const long long p0  = (long long)blockIdx.x * TILE;
    const int       b   = (int)(p0 / HW);
    const int       hw0 = (int)(p0 % HW);

    // ---- stage weights (natural layout) and bias ----
    #pragma unroll
    for (int i = tid; i < CIN * COUT / 4; i += NTHREADS) {
        *(float4*)(wn + i * 4) = *(const float4*)(Wg + i * 4);
    }
    if (tid < COUT) bs[tid] = bias[tid];

    // ---- stage x tile: 32 channels x 128 pixels, float4 global loads ----
    const float* xb = x + (long long)b * CIN * HW + hw0;
    #pragma unroll
    for (int i = tid; i < CIN * (TILE / 4); i += NTHREADS) {
        int c = i >> 5;      // i / (TILE/4)
        int q = i & 31;      // i % (TILE/4)
        float4 v = *(const float4*)(xb + (long long)c * HW + q * 4);
        *(float4*)(&xs[c * TILE + q * 4]) = v;
    }
    __syncthreads();

    // thread mapping: warp id -> output group of 8, lane -> pixel group of 4
    const int og = tid >> 5;   // 0..7  (uniform per warp -> w loads broadcast)
    const int pg = tid & 31;   // 0..31 (lane -> 4 consecutive pixels)

    // acc[p][j]: pixel p (0..3), output-pair j (0..3): lanes = (out o0+2j, o0+2j+1)
    unsigned long long acc[4][4];
    #pragma unroll
    for (int p = 0; p < 4; ++p)
        #pragma unroll
        for (int j = 0; j < 4; ++j) acc[p][j] = 0ULL;

    // per-pixel activity: OR of |x| bit patterns
    unsigned m0 = 0u, m1 = 0u, m2 = 0u, m3 = 0u;
    const unsigned ABSM = 0x7FFFFFFFu;

    const float* xsp = xs + pg * 4;
    const float* wsp = wn + og * 8;

    #pragma unroll
    for (int c = 0; c < CIN; ++c) {
        // 4 pixels of x (one LDS.128, conflict-free: 16B lane stride)
        float4 xv = *(const float4*)(xsp + c * TILE);
        m0 |= __float_as_uint(xv.x) & ABSM;
        m1 |= __float_as_uint(xv.y) & ABSM;
        m2 |= __float_as_uint(xv.z) & ABSM;
        m3 |= __float_as_uint(xv.w) & ABSM;

        unsigned long long xx0 = dup2(xv.x);
        unsigned long long xx1 = dup2(xv.y);
        unsigned long long xx2 = dup2(xv.z);
        unsigned long long xx3 = dup2(xv.w);

        // 8 natural weights for this channel: 2 broadcast LDS.128
        const ulonglong2* wrow = (const ulonglong2*)(wsp + c * COUT);
        ulonglong2 wa = wrow[0];   // pairs (w0,w1), (w2,w3)
        ulonglong2 wb = wrow[1];   // pairs (w4,w5), (w6,w7)

        fma2(acc[0][0], xx0, wa.x);  fma2(acc[0][1], xx0, wa.y);
        fma2(acc[0][2], xx0, wb.x);  fma2(acc[0][3], xx0, wb.y);
        fma2(acc[1][0], xx1, wa.x);  fma2(acc[1][1], xx1, wa.y);
        fma2(acc[1][2], xx1, wb.x);  fma2(acc[1][3], xx1, wb.y);
        fma2(acc[2][0], xx2, wa.x);  fma2(acc[2][1], xx2, wa.y);
        fma2(acc[2][2], xx2, wb.x);  fma2(acc[2][3], xx2, wb.y);
        fma2(acc[3][0], xx3, wa.x);  fma2(acc[3][1], xx3, wa.y);
        fma2(acc[3][2], xx3, wb.x);  fma2(acc[3][3], xx3, wb.y);
    }

    const bool a0 = (m0 != 0u);
    const bool a1 = (m1 != 0u);
    const bool a2 = (m2 != 0u);
    const bool a3 = (m3 != 0u);

    // ---- epilogue: add bias pairs, mask per pixel, STG.128 per output ----
    float* ob = out + ((long long)b * COUT) * HW + hw0 + pg * 4;
    const ulonglong2* bp = (const ulonglong2*)(bs + og * 8);
    ulonglong2 ba = bp[0];   // (b0,b1),(b2,b3)
    ulonglong2 bb = bp[1];   // (b4,b5),(b6,b7)
    unsigned long long bpair[4] = { ba.x, ba.y, bb.x, bb.y };

    #pragma unroll
    for (int j = 0; j < 4; ++j) {
        unsigned long long s0 = a0 ? add2(acc[0][j], bpair[j]) : 0ULL;
        unsigned long long s1 = a1 ? add2(acc[1][j], bpair[j]) : 0ULL;
        unsigned long long s2 = a2 ? add2(acc[2][j], bpair[j]) : 0ULL;
        unsigned long long s3 = a3 ? add2(acc[3][j], bpair[j]) : 0ULL;

        float2 f0 = *(float2*)&s0;
        float2 f1 = *(float2*)&s1;
        float2 f2 = *(float2*)&s2;
        float2 f3 = *(float2*)&s3;

        int o0 = og * 8 + 2 * j;
        float4 rlo = make_float4(f0.x, f1.x, f2.x, f3.x);  // output o0, px 0..3
        float4 rhi = make_float4(f0.y, f1.y, f2.y, f3.y);  // output o0+1
        *(float4*)(ob + (long long)o0 * HW)       = rlo;
        *(float4*)(ob + (long long)(o0 + 1) * HW) = rhi;
    }
}

extern "C" void kernel_launch(void* const* d_in, const int* in_sizes, int n_in,
                              void* d_out, int out_size) {
    const float* x  = (const float*)d_in[0];
    const float* Wg = (const float*)d_in[1];
    const float* bi = (const float*)d_in[2];
    float* out = (float*)d_out;

    const int smem_bytes = SMEM_FLOATS * (int)sizeof(float);  // ~24.3 KB
    cudaFuncSetAttribute(spconv_pw_kernel,
                         cudaFuncAttributeMaxDynamicSharedMemorySize, smem_bytes);

    const int grid = NPIX / TILE;   // 16384
    spconv_pw_kernel<<<grid, NTHREADS, smem_bytes>>>(x, Wg, bi, out);
}